// round 3
// baseline (speedup 1.0000x reference)
#include <cuda_runtime.h>

// SimpleGRU: B=2048, T=2048, H=32, scalar input.
// 2 warps per batch element (producer/consumer j-split):
//   warp1: matvec over h[16:32] for all 3 gates + entire x-side -> float4 partials
//   warp0: matvec over h[0:16], combine, gate math, owns h (lane i = unit i)
// Activation scale constants folded into preloaded weights:
//   r,z rows scaled by -log2(e); n rows (and n x-side, b_hh_n) scaled by 2*log2(e).

#define FULL_MASK 0xffffffffu
using u64 = unsigned long long;

__device__ __forceinline__ float fast_ex2(float x) {
    float y; asm("ex2.approx.f32 %0, %1;" : "=f"(y) : "f"(x)); return y;
}
__device__ __forceinline__ float fast_rcp(float x) {
    float y; asm("rcp.approx.f32 %0, %1;" : "=f"(y) : "f"(x)); return y;
}
__device__ __forceinline__ void ffma2(u64& d, u64 a, u64 b, u64 c) {
    asm("fma.rn.f32x2 %0, %1, %2, %3;" : "=l"(d) : "l"(a), "l"(b), "l"(c));
}
__device__ __forceinline__ float2 unpk(u64 v) {
    float2 f; asm("mov.b64 {%0, %1}, %2;" : "=f"(f.x), "=f"(f.y) : "l"(v)); return f;
}
__device__ __forceinline__ u64 pk(float x, float y) {
    u64 d; asm("mov.b64 %0, {%1, %2};" : "=l"(d) : "f"(x), "f"(y)); return d;
}
__device__ __forceinline__ void barrier64() {
    asm volatile("bar.sync 0, 64;" ::: "memory");
}

__global__ void __launch_bounds__(64, 14)
gru_kernel(const float* __restrict__ x,
           const float* __restrict__ w_ih,
           const float* __restrict__ w_hh,
           const float* __restrict__ b_ih,
           const float* __restrict__ b_hh,
           const float* __restrict__ head_w,
           const float* __restrict__ head_b,
           float* __restrict__ out,
           int B, int T)
{
    const int b   = blockIdx.x;
    const int tid = threadIdx.x;
    const int w   = tid >> 5;       // 0 = consumer, 1 = producer
    const int i   = tid & 31;       // lane == hidden unit index

    __shared__ __align__(16) float  hsh[2][32];   // double-buffered h
    __shared__ __align__(16) float4 part[32];     // producer partials

    const float SR = -1.44269504088896340736f;    // -log2(e)
    const float SN =  2.88539008177792681472f;    //  2*log2(e)

    // Per-lane W_hh rows (unit i), j-half [16w, 16w+16), prescaled, packed f32x2.
    u64 wr2[8], wz2[8], wn2[8];
    {
        const float2* Wr = (const float2*)(w_hh + (0  + i) * 32 + 16 * w);
        const float2* Wz = (const float2*)(w_hh + (32 + i) * 32 + 16 * w);
        const float2* Wn = (const float2*)(w_hh + (64 + i) * 32 + 16 * w);
        #pragma unroll
        for (int j = 0; j < 8; j++) {
            float2 vr = Wr[j]; wr2[j] = pk(vr.x * SR, vr.y * SR);
            float2 vz = Wz[j]; wz2[j] = pk(vz.x * SR, vz.y * SR);
            float2 vn = Wn[j]; wn2[j] = pk(vn.x * SN, vn.y * SN);
        }
    }

    if (w == 0) hsh[0][i] = 0.0f;   // h0 = 0
    __syncthreads();

    const float* xb = x + (long long)b * T;

    if (w == 1) {
        // ---------------- producer: upper j-half + full x-side ----------------
        const float wirc = w_ih[i]      * SR;
        const float crc  = (b_ih[i]      + b_hh[i])      * SR;
        const float wizc = w_ih[32 + i] * SR;
        const float czc  = (b_ih[32 + i] + b_hh[32 + i]) * SR;
        const float winc = w_ih[64 + i] * SN;
        const float cnxc = b_ih[64 + i] * SN;
        const float cnhc = b_hh[64 + i] * SN;   // h-side n bias (scaled by r later)

        int rb = 0;
        for (int t0 = 0; t0 < T; t0 += 32) {
            float xq = xb[t0 + i];
            #pragma unroll 4
            for (int k = 0; k < 32; k++) {
                float xt = __shfl_sync(FULL_MASK, xq, k);

                const u64* hp = (const u64*)hsh[rb] + 8;   // h[16:32], broadcast LDS
                u64 ar = 0, az = 0, an = pk(cnhc, 0.0f);
                #pragma unroll
                for (int j = 0; j < 8; j++) {
                    u64 h2 = hp[j];
                    ffma2(ar, wr2[j], h2, ar);
                    ffma2(az, wz2[j], h2, az);
                    ffma2(an, wn2[j], h2, an);
                }
                float2 fr = unpk(ar), fz = unpk(az), fn = unpk(an);
                float pr1 = fr.x + fr.y + fmaf(xt, wirc, crc);
                float pz1 = fz.x + fz.y + fmaf(xt, wizc, czc);
                float pn1 = fn.x + fn.y;                    // h-side n (scaled)
                float xn1 = fmaf(xt, winc, cnxc);           // x-side n (scaled)
                part[i] = make_float4(pr1, pz1, pn1, xn1);

                barrier64();            // partials visible to consumer
                barrier64();            // h_new visible from consumer
                rb ^= 1;
            }
        }
    } else {
        // ---------------- consumer: lower j-half + gate math ----------------
        float h = 0.0f;
        int rb = 0;
        for (int t0 = 0; t0 < T; t0 += 32) {
            #pragma unroll 4
            for (int k = 0; k < 32; k++) {
                const u64* hp = (const u64*)hsh[rb];        // h[0:16], broadcast LDS
                u64 ar = 0, az = 0, an = 0;
                #pragma unroll
                for (int j = 0; j < 8; j++) {
                    u64 h2 = hp[j];
                    ffma2(ar, wr2[j], h2, ar);
                    ffma2(az, wz2[j], h2, az);
                    ffma2(an, wn2[j], h2, an);
                }
                barrier64();            // wait for producer partials

                float4 p  = part[i];
                float2 fr = unpk(ar), fz = unpk(az), fn = unpk(an);
                float sr_ = fr.x + fr.y + p.x;              // -log2e * r-preact
                float sz_ = fz.x + fz.y + p.y;              // -log2e * z-preact
                float hn  = fn.x + fn.y + p.z;              // 2log2e * h-side n

                float r = fast_rcp(1.0f + fast_ex2(sr_));
                float z = fast_rcp(1.0f + fast_ex2(sz_));
                float narg = fmaf(r, hn, p.w);              // 2log2e * n-preact
                float n = fmaf(-2.0f, fast_rcp(fast_ex2(narg) + 1.0f), 1.0f);
                h = fmaf(z, h - n, n);                      // (1-z)*n + z*h

                hsh[rb ^ 1][i] = h;
                barrier64();            // h_new visible to producer
                rb ^= 1;
            }
        }

        // Head: out[b][o] = sum_i h_i * head_w[o][i] + head_b[o], O = 2
        float p0 = h * head_w[i];
        float p1 = h * head_w[32 + i];
        #pragma unroll
        for (int m = 16; m > 0; m >>= 1) {
            p0 += __shfl_xor_sync(FULL_MASK, p0, m);
            p1 += __shfl_xor_sync(FULL_MASK, p1, m);
        }
        if (i == 0) {
            out[2 * b]     = p0 + head_b[0];
            out[2 * b + 1] = p1 + head_b[1];
        }
    }
}

extern "C" void kernel_launch(void* const* d_in, const int* in_sizes, int n_in,
                              void* d_out, int out_size) {
    const float* x      = (const float*)d_in[0];
    const float* w_ih   = (const float*)d_in[1];
    const float* w_hh   = (const float*)d_in[2];
    const float* b_ih   = (const float*)d_in[3];
    const float* b_hh   = (const float*)d_in[4];
    const float* head_w = (const float*)d_in[5];
    const float* head_b = (const float*)d_in[6];
    float* out = (float*)d_out;

    const int B = out_size / 2;           // 2048
    const int T = in_sizes[0] / B;        // 2048

    gru_kernel<<<B, 64>>>(x, w_ih, w_hh, b_ih, b_hh, head_w, head_b, out, B, T);
}

// round 4
// speedup vs baseline: 1.1022x; 1.1022x over previous
#include <cuda_runtime.h>
#include <cuda_fp16.h>

// SimpleGRU: B=2048, T=2048, H=32, scalar input.
// One warp per batch; lane i owns hidden unit i.
// Matvec in fp16 (HFMA2, rt2 = 2x fp32 MAC throughput):
//   W_hh rows prescaled (-log2e for r,z; 2log2e for n), packed half2 in regs.
//   h broadcast as fp16 through a 64B shared buffer.
//   4 accumulators per gate (depth-4 chains) + HADD2 tree -> fp32 finish.
// Gate math stays fp32 (ex2/rcp approx).

#define FULL_MASK 0xffffffffu

__device__ __forceinline__ float fast_ex2(float x) {
    float y; asm("ex2.approx.f32 %0, %1;" : "=f"(y) : "f"(x)); return y;
}
__device__ __forceinline__ float fast_rcp(float x) {
    float y; asm("rcp.approx.f32 %0, %1;" : "=f"(y) : "f"(x)); return y;
}

__global__ void __launch_bounds__(32, 14)
gru_kernel(const float* __restrict__ x,
           const float* __restrict__ w_ih,
           const float* __restrict__ w_hh,
           const float* __restrict__ b_ih,
           const float* __restrict__ b_hh,
           const float* __restrict__ head_w,
           const float* __restrict__ head_b,
           float* __restrict__ out,
           int B, int T)
{
    const int b = blockIdx.x;
    const int i = threadIdx.x;              // lane == hidden unit, H == 32

    __shared__ __align__(16) __half hsh[32];   // h broadcast buffer (64B)

    const float SR = -1.44269504088896340736f;  // -log2(e)
    const float SN =  2.88539008177792681472f;  //  2*log2(e)

    // Preload prescaled W_hh rows for unit i as half2 pairs (j-pairs).
    __half2 wr2[16], wz2[16], wn2[16];
    {
        const float* Wr = w_hh + (0  + i) * 32;
        const float* Wz = w_hh + (32 + i) * 32;
        const float* Wn = w_hh + (64 + i) * 32;
        #pragma unroll
        for (int j = 0; j < 16; j++) {
            wr2[j] = __floats2half2_rn(Wr[2*j] * SR, Wr[2*j+1] * SR);
            wz2[j] = __floats2half2_rn(Wz[2*j] * SR, Wz[2*j+1] * SR);
            wn2[j] = __floats2half2_rn(Wn[2*j] * SN, Wn[2*j+1] * SN);
        }
    }

    // x-side constants, prescaled, fp32.
    const float wirc = w_ih[i]      * SR;
    const float crc  = (b_ih[i]      + b_hh[i])      * SR;
    const float wizc = w_ih[32 + i] * SR;
    const float czc  = (b_ih[32 + i] + b_hh[32 + i]) * SR;
    const float winc = w_ih[64 + i] * SN;
    const float cnxc = b_ih[64 + i] * SN;
    const float cnhc = b_hh[64 + i] * SN;     // h-side n bias (multiplied by r)

    float h = 0.0f;
    const float* xb = x + (long long)b * T;

    for (int t0 = 0; t0 < T; t0 += 32) {
        float xq = xb[t0 + i];                // 32 timesteps, one per lane
        #pragma unroll 4
        for (int k = 0; k < 32; k++) {
            float xt = __shfl_sync(FULL_MASK, xq, k);

            __syncwarp();                     // previous step's readers done
            hsh[i] = __float2half(h);
            __syncwarp();                     // h vector visible

            const __half2* hp = (const __half2*)hsh;   // 16 half2, broadcast LDS
            __half2 z2 = __float2half2_rn(0.0f);
            __half2 ar[4] = {z2, z2, z2, z2};
            __half2 az[4] = {z2, z2, z2, z2};
            __half2 an[4] = {z2, z2, z2, z2};
            #pragma unroll
            for (int j = 0; j < 16; j++) {
                __half2 h2 = hp[j];
                const int c = j & 3;          // 4 chains, depth 4
                ar[c] = __hfma2(wr2[j], h2, ar[c]);
                az[c] = __hfma2(wz2[j], h2, az[c]);
                an[c] = __hfma2(wn2[j], h2, an[c]);
            }
            __half2 sr2 = __hadd2(__hadd2(ar[0], ar[1]), __hadd2(ar[2], ar[3]));
            __half2 sz2 = __hadd2(__hadd2(az[0], az[1]), __hadd2(az[2], az[3]));
            __half2 sn2 = __hadd2(__hadd2(an[0], an[1]), __hadd2(an[2], an[3]));
            float2 fr = __half22float2(sr2);
            float2 fz = __half22float2(sz2);
            float2 fn = __half22float2(sn2);

            float sr_ = fr.x + fr.y + fmaf(xt, wirc, crc);  // -log2e * r-preact
            float sz_ = fz.x + fz.y + fmaf(xt, wizc, czc);  // -log2e * z-preact
            float hn  = fn.x + fn.y + cnhc;                 // 2log2e * h-side n

            float r = fast_rcp(1.0f + fast_ex2(sr_));
            float z = fast_rcp(1.0f + fast_ex2(sz_));
            float narg = fmaf(r, hn, fmaf(xt, winc, cnxc)); // 2log2e * n-preact
            float n = fmaf(-2.0f, fast_rcp(fast_ex2(narg) + 1.0f), 1.0f);
            h = fmaf(z, h - n, n);                          // (1-z)*n + z*h
        }
    }

    // Head: out[b][o] = sum_i h_i * head_w[o][i] + head_b[o],  O = 2  (fp32)
    float p0 = h * head_w[i];
    float p1 = h * head_w[32 + i];
    #pragma unroll
    for (int m = 16; m > 0; m >>= 1) {
        p0 += __shfl_xor_sync(FULL_MASK, p0, m);
        p1 += __shfl_xor_sync(FULL_MASK, p1, m);
    }
    if (i == 0) {
        out[2 * b]     = p0 + head_b[0];
        out[2 * b + 1] = p1 + head_b[1];
    }
}

extern "C" void kernel_launch(void* const* d_in, const int* in_sizes, int n_in,
                              void* d_out, int out_size) {
    const float* x      = (const float*)d_in[0];
    const float* w_ih   = (const float*)d_in[1];
    const float* w_hh   = (const float*)d_in[2];
    const float* b_ih   = (const float*)d_in[3];
    const float* b_hh   = (const float*)d_in[4];
    const float* head_w = (const float*)d_in[5];
    const float* head_b = (const float*)d_in[6];
    float* out = (float*)d_out;

    const int B = out_size / 2;           // 2048
    const int T = in_sizes[0] / B;        // 2048

    gru_kernel<<<B, 32>>>(x, w_ih, w_hh, b_ih, b_hh, head_w, head_b, out, B, T);
}

// round 5
// speedup vs baseline: 1.2566x; 1.1401x over previous
#include <cuda_runtime.h>
#include <cuda_fp16.h>

// SimpleGRU: B=2048, T=2048, H=32, scalar input.
// One warp handles TWO batch elements (independent chains -> in-warp ILP).
// Lane i owns hidden unit i of both. Matvec in fp16 HFMA2, weights shared
// between the two batches (prescaled: -log2e for r,z; 2log2e for n).
// h broadcast via double-buffered smem (single syncwarp/step, 8x LDS.128).
// Gate math fp32 (ex2/rcp approx).

#define FULL_MASK 0xffffffffu

__device__ __forceinline__ float fast_ex2(float x) {
    float y; asm("ex2.approx.f32 %0, %1;" : "=f"(y) : "f"(x)); return y;
}
__device__ __forceinline__ float fast_rcp(float x) {
    float y; asm("rcp.approx.f32 %0, %1;" : "=f"(y) : "f"(x)); return y;
}
__device__ __forceinline__ __half2 u2h(unsigned int u) {
    return *reinterpret_cast<const __half2*>(&u);
}

__global__ void __launch_bounds__(32)
gru_kernel(const float* __restrict__ x,
           const float* __restrict__ w_ih,
           const float* __restrict__ w_hh,
           const float* __restrict__ b_ih,
           const float* __restrict__ b_hh,
           const float* __restrict__ head_w,
           const float* __restrict__ head_b,
           float* __restrict__ out,
           int B, int T)
{
    const int b0 = blockIdx.x * 2;          // two batch elements per warp
    const int i  = threadIdx.x;             // lane == hidden unit, H == 32

    // [buffer parity][ batchA h (32) | batchB h (32) ]
    __shared__ __align__(16) __half hsh[2][64];

    const float SR = -1.44269504088896340736f;  // -log2(e)
    const float SN =  2.88539008177792681472f;  //  2*log2(e)

    // Prescaled W_hh rows for unit i, packed half2 (shared by both batches).
    __half2 wr2[16], wz2[16], wn2[16];
    {
        const float* Wr = w_hh + (0  + i) * 32;
        const float* Wz = w_hh + (32 + i) * 32;
        const float* Wn = w_hh + (64 + i) * 32;
        #pragma unroll
        for (int j = 0; j < 16; j++) {
            wr2[j] = __floats2half2_rn(Wr[2*j] * SR, Wr[2*j+1] * SR);
            wz2[j] = __floats2half2_rn(Wz[2*j] * SR, Wz[2*j+1] * SR);
            wn2[j] = __floats2half2_rn(Wn[2*j] * SN, Wn[2*j+1] * SN);
        }
    }

    // Prescaled x-side constants (fp32) and n-gate h-side bias folded to half2.
    const float   wirc = w_ih[i]      * SR;
    const float   crc  = (b_ih[i]      + b_hh[i])      * SR;
    const float   wizc = w_ih[32 + i] * SR;
    const float   czc  = (b_ih[32 + i] + b_hh[32 + i]) * SR;
    const float   winc = w_ih[64 + i] * SN;
    const float   cnxc = b_ih[64 + i] * SN;
    const __half2 cnh2 = __floats2half2_rn(b_hh[64 + i] * SN, 0.0f);

    float ha = 0.0f, hb = 0.0f;
    const float* xA = x + (long long)b0 * T;
    const float* xB = xA + T;

    for (int t0 = 0; t0 < T; t0 += 32) {
        float xqa = xA[t0 + i];             // 32 timesteps per lane, both batches
        float xqb = xB[t0 + i];
        #pragma unroll 4
        for (int k = 0; k < 32; k++) {
            float xta = __shfl_sync(FULL_MASK, xqa, k);
            float xtb = __shfl_sync(FULL_MASK, xqb, k);
            const int p = k & 1;            // buffer parity

            hsh[p][i]      = __float2half(ha);
            hsh[p][32 + i] = __float2half(hb);
            __syncwarp();                   // store visible; WAR safe via parity

            // 8x LDS.128 broadcast: both h vectors (16 half2 each).
            const uint4* hp = (const uint4*)&hsh[p][0];
            uint4 a0 = hp[0], a1 = hp[1], a2 = hp[2], a3 = hp[3];
            uint4 v0 = hp[4], v1 = hp[5], v2 = hp[6], v3 = hp[7];
            unsigned int Ha[16] = {a0.x,a0.y,a0.z,a0.w, a1.x,a1.y,a1.z,a1.w,
                                   a2.x,a2.y,a2.z,a2.w, a3.x,a3.y,a3.z,a3.w};
            unsigned int Hb[16] = {v0.x,v0.y,v0.z,v0.w, v1.x,v1.y,v1.z,v1.w,
                                   v2.x,v2.y,v2.z,v2.w, v3.x,v3.y,v3.z,v3.w};

            // ---- batch A matvec: 2 chains/gate, depth 8 ----
            __half2 ar0 = __hmul2(wr2[0], u2h(Ha[0]));
            __half2 ar1 = __hmul2(wr2[1], u2h(Ha[1]));
            __half2 az0 = __hmul2(wz2[0], u2h(Ha[0]));
            __half2 az1 = __hmul2(wz2[1], u2h(Ha[1]));
            __half2 an0 = __hfma2(wn2[0], u2h(Ha[0]), cnh2);
            __half2 an1 = __hmul2(wn2[1], u2h(Ha[1]));
            // ---- batch B matvec ----
            __half2 br0 = __hmul2(wr2[0], u2h(Hb[0]));
            __half2 br1 = __hmul2(wr2[1], u2h(Hb[1]));
            __half2 bz0 = __hmul2(wz2[0], u2h(Hb[0]));
            __half2 bz1 = __hmul2(wz2[1], u2h(Hb[1]));
            __half2 bn0 = __hfma2(wn2[0], u2h(Hb[0]), cnh2);
            __half2 bn1 = __hmul2(wn2[1], u2h(Hb[1]));
            #pragma unroll
            for (int j = 2; j < 16; j += 2) {
                __half2 ga0 = u2h(Ha[j]), ga1 = u2h(Ha[j+1]);
                __half2 gb0 = u2h(Hb[j]), gb1 = u2h(Hb[j+1]);
                ar0 = __hfma2(wr2[j],   ga0, ar0);
                ar1 = __hfma2(wr2[j+1], ga1, ar1);
                az0 = __hfma2(wz2[j],   ga0, az0);
                az1 = __hfma2(wz2[j+1], ga1, az1);
                an0 = __hfma2(wn2[j],   ga0, an0);
                an1 = __hfma2(wn2[j+1], ga1, an1);
                br0 = __hfma2(wr2[j],   gb0, br0);
                br1 = __hfma2(wr2[j+1], gb1, br1);
                bz0 = __hfma2(wz2[j],   gb0, bz0);
                bz1 = __hfma2(wz2[j+1], gb1, bz1);
                bn0 = __hfma2(wn2[j],   gb0, bn0);
                bn1 = __hfma2(wn2[j+1], gb1, bn1);
            }

            // ---- batch A gates (fp32) ----
            {
                float2 fr = __half22float2(__hadd2(ar0, ar1));
                float2 fz = __half22float2(__hadd2(az0, az1));
                float2 fn = __half22float2(__hadd2(an0, an1));
                float sr_ = fr.x + fr.y + fmaf(xta, wirc, crc);
                float sz_ = fz.x + fz.y + fmaf(xta, wizc, czc);
                float hn  = fn.x + fn.y;
                float r = fast_rcp(1.0f + fast_ex2(sr_));
                float z = fast_rcp(1.0f + fast_ex2(sz_));
                float narg = fmaf(r, hn, fmaf(xta, winc, cnxc));
                float n = fmaf(-2.0f, fast_rcp(fast_ex2(narg) + 1.0f), 1.0f);
                ha = fmaf(z, ha - n, n);
            }
            // ---- batch B gates (fp32) ----
            {
                float2 fr = __half22float2(__hadd2(br0, br1));
                float2 fz = __half22float2(__hadd2(bz0, bz1));
                float2 fn = __half22float2(__hadd2(bn0, bn1));
                float sr_ = fr.x + fr.y + fmaf(xtb, wirc, crc);
                float sz_ = fz.x + fz.y + fmaf(xtb, wizc, czc);
                float hn  = fn.x + fn.y;
                float r = fast_rcp(1.0f + fast_ex2(sr_));
                float z = fast_rcp(1.0f + fast_ex2(sz_));
                float narg = fmaf(r, hn, fmaf(xtb, winc, cnxc));
                float n = fmaf(-2.0f, fast_rcp(fast_ex2(narg) + 1.0f), 1.0f);
                hb = fmaf(z, hb - n, n);
            }
        }
    }

    // Head for both batches: out[b][o] = sum_i h_i * head_w[o][i] + head_b[o]
    float p0a = ha * head_w[i], p1a = ha * head_w[32 + i];
    float p0b = hb * head_w[i], p1b = hb * head_w[32 + i];
    #pragma unroll
    for (int m = 16; m > 0; m >>= 1) {
        p0a += __shfl_xor_sync(FULL_MASK, p0a, m);
        p1a += __shfl_xor_sync(FULL_MASK, p1a, m);
        p0b += __shfl_xor_sync(FULL_MASK, p0b, m);
        p1b += __shfl_xor_sync(FULL_MASK, p1b, m);
    }
    if (i == 0) {
        out[2 * b0]     = p0a + head_b[0];
        out[2 * b0 + 1] = p1a + head_b[1];
        out[2 * b0 + 2] = p0b + head_b[0];
        out[2 * b0 + 3] = p1b + head_b[1];
    }
}

extern "C" void kernel_launch(void* const* d_in, const int* in_sizes, int n_in,
                              void* d_out, int out_size) {
    const float* x      = (const float*)d_in[0];
    const float* w_ih   = (const float*)d_in[1];
    const float* w_hh   = (const float*)d_in[2];
    const float* b_ih   = (const float*)d_in[3];
    const float* b_hh   = (const float*)d_in[4];
    const float* head_w = (const float*)d_in[5];
    const float* head_b = (const float*)d_in[6];
    float* out = (float*)d_out;

    const int B = out_size / 2;           // 2048
    const int T = in_sizes[0] / B;        // 2048

    gru_kernel<<<B / 2, 32>>>(x, w_ih, w_hh, b_ih, b_hh, head_w, head_b, out, B, T);
}

// round 6
// speedup vs baseline: 1.5382x; 1.2241x over previous
#include <cuda_runtime.h>
#include <cuda_fp16.h>

// SimpleGRU: B=2048, T=2048, H=32, scalar input.
// One warp = two batch elements; lane i = hidden unit i (both batches).
// Matvec: fp16 HFMA2, j-pair packed, weights shared across the 2 batches.
//   r,z rows prescaled by 0.5 (sigmoid-via-tanh), n rows unscaled.
// Gate tail: fully packed half2 over {batchA, batchB}:
//   combine via PRMT lows/highs (alu pipe), tanh.approx.f16x2 activations.
// h carried in fp32 per batch; broadcast as fp16 via double-buffered smem.

#define FULL_MASK 0xffffffffu

__device__ __forceinline__ __half2 htanh2(__half2 a) {
    unsigned int d, s = *reinterpret_cast<unsigned int*>(&a);
    asm("tanh.approx.f16x2 %0, %1;" : "=r"(d) : "r"(s));
    return *reinterpret_cast<__half2*>(&d);
}
__device__ __forceinline__ __half2 u2h(unsigned int u) {
    return *reinterpret_cast<const __half2*>(&u);
}

__global__ void __launch_bounds__(32)
gru_kernel(const float* __restrict__ x,
           const float* __restrict__ w_ih,
           const float* __restrict__ w_hh,
           const float* __restrict__ b_ih,
           const float* __restrict__ b_hh,
           const float* __restrict__ head_w,
           const float* __restrict__ head_b,
           float* __restrict__ out,
           int B, int T)
{
    const int b0 = blockIdx.x * 2;          // two batch elements per warp
    const int i  = threadIdx.x;             // lane == hidden unit, H == 32

    // [buffer parity][ batchA h (32) | batchB h (32) ]
    __shared__ __align__(16) __half hsh[2][64];

    const float SRZ = 0.5f;                 // sigmoid(t) = 0.5 + 0.5*tanh(0.5*t)

    // Prescaled W_hh rows for unit i, packed half2 j-pairs (shared by A and B).
    __half2 wr2[16], wz2[16], wn2[16];
    {
        const float* Wr = w_hh + (0  + i) * 32;
        const float* Wz = w_hh + (32 + i) * 32;
        const float* Wn = w_hh + (64 + i) * 32;
        #pragma unroll
        for (int j = 0; j < 16; j++) {
            wr2[j] = __floats2half2_rn(Wr[2*j] * SRZ, Wr[2*j+1] * SRZ);
            wz2[j] = __floats2half2_rn(Wz[2*j] * SRZ, Wz[2*j+1] * SRZ);
            wn2[j] = __floats2half2_rn(Wn[2*j], Wn[2*j+1]);
        }
    }

    // x-side constants, duplicated into both half2 lanes (A and B share them).
    const __half2 wir2 = __float2half2_rn(w_ih[i]      * SRZ);
    const __half2 cr2  = __float2half2_rn((b_ih[i]      + b_hh[i])      * SRZ);
    const __half2 wiz2 = __float2half2_rn(w_ih[32 + i] * SRZ);
    const __half2 cz2  = __float2half2_rn((b_ih[32 + i] + b_hh[32 + i]) * SRZ);
    const __half2 win2 = __float2half2_rn(w_ih[64 + i]);
    const __half2 cnx2 = __float2half2_rn(b_ih[64 + i]);
    const __half2 cnh2 = __floats2half2_rn(b_hh[64 + i], 0.0f);  // summed once
    const __half2 hlf2 = __float2half2_rn(0.5f);

    float ha = 0.0f, hb = 0.0f;
    const float* xA = x + (long long)b0 * T;
    const float* xB = xA + T;

    for (int t0 = 0; t0 < T; t0 += 32) {
        float xqa = xA[t0 + i];             // 32 timesteps per lane, both batches
        float xqb = xB[t0 + i];
        #pragma unroll 4
        for (int k = 0; k < 32; k++) {
            float xta = __shfl_sync(FULL_MASK, xqa, k);
            float xtb = __shfl_sync(FULL_MASK, xqb, k);
            const int p = k & 1;            // buffer parity

            hsh[p][i]      = __float2half(ha);
            hsh[p][32 + i] = __float2half(hb);
            __syncwarp();                   // store visible; WAR safe via parity

            // 8x LDS.128 broadcast: both h vectors (16 half2 each).
            const uint4* hp = (const uint4*)&hsh[p][0];
            uint4 a0 = hp[0], a1 = hp[1], a2 = hp[2], a3 = hp[3];
            uint4 v0 = hp[4], v1 = hp[5], v2 = hp[6], v3 = hp[7];
            unsigned int Ha[16] = {a0.x,a0.y,a0.z,a0.w, a1.x,a1.y,a1.z,a1.w,
                                   a2.x,a2.y,a2.z,a2.w, a3.x,a3.y,a3.z,a3.w};
            unsigned int Hb[16] = {v0.x,v0.y,v0.z,v0.w, v1.x,v1.y,v1.z,v1.w,
                                   v2.x,v2.y,v2.z,v2.w, v3.x,v3.y,v3.z,v3.w};

            // ---- matvec: 2 chains/gate/batch, depth 8 ----
            __half2 ar0 = __hmul2(wr2[0], u2h(Ha[0]));
            __half2 ar1 = __hmul2(wr2[1], u2h(Ha[1]));
            __half2 az0 = __hmul2(wz2[0], u2h(Ha[0]));
            __half2 az1 = __hmul2(wz2[1], u2h(Ha[1]));
            __half2 an0 = __hfma2(wn2[0], u2h(Ha[0]), cnh2);
            __half2 an1 = __hmul2(wn2[1], u2h(Ha[1]));
            __half2 br0 = __hmul2(wr2[0], u2h(Hb[0]));
            __half2 br1 = __hmul2(wr2[1], u2h(Hb[1]));
            __half2 bz0 = __hmul2(wz2[0], u2h(Hb[0]));
            __half2 bz1 = __hmul2(wz2[1], u2h(Hb[1]));
            __half2 bn0 = __hfma2(wn2[0], u2h(Hb[0]), cnh2);
            __half2 bn1 = __hmul2(wn2[1], u2h(Hb[1]));
            #pragma unroll
            for (int j = 2; j < 16; j += 2) {
                __half2 ga0 = u2h(Ha[j]), ga1 = u2h(Ha[j+1]);
                __half2 gb0 = u2h(Hb[j]), gb1 = u2h(Hb[j+1]);
                ar0 = __hfma2(wr2[j],   ga0, ar0);
                ar1 = __hfma2(wr2[j+1], ga1, ar1);
                az0 = __hfma2(wz2[j],   ga0, az0);
                az1 = __hfma2(wz2[j+1], ga1, az1);
                an0 = __hfma2(wn2[j],   ga0, an0);
                an1 = __hfma2(wn2[j+1], ga1, an1);
                br0 = __hfma2(wr2[j],   gb0, br0);
                br1 = __hfma2(wr2[j+1], gb1, br1);
                bz0 = __hfma2(wz2[j],   gb0, bz0);
                bz1 = __hfma2(wz2[j+1], gb1, bz1);
                bn0 = __hfma2(wn2[j],   gb0, bn0);
                bn1 = __hfma2(wn2[j+1], gb1, bn1);
            }

            // ---- combine into packed {A, B} per gate (PRMT on alu pipe) ----
            __half2 arx = __hadd2(ar0, ar1);        // {evenA, oddA}
            __half2 brx = __hadd2(br0, br1);
            __half2 azx = __hadd2(az0, az1);
            __half2 bzx = __hadd2(bz0, bz1);
            __half2 anx = __hadd2(an0, an1);
            __half2 bnx = __hadd2(bn0, bn1);
            __half2 hr2 = __hadd2(__lows2half2(arx, brx), __highs2half2(arx, brx));
            __half2 hz2 = __hadd2(__lows2half2(azx, bzx), __highs2half2(azx, bzx));
            __half2 hn2 = __hadd2(__lows2half2(anx, bnx), __highs2half2(anx, bnx));

            // ---- packed gate math over {A, B} ----
            __half2 xt2 = __floats2half2_rn(xta, xtb);
            __half2 pre_r = __hadd2(hr2, __hfma2(xt2, wir2, cr2));  // 0.5*preact
            __half2 pre_z = __hadd2(hz2, __hfma2(xt2, wiz2, cz2));
            __half2 r2 = __hfma2(htanh2(pre_r), hlf2, hlf2);        // sigmoid
            __half2 z2 = __hfma2(htanh2(pre_z), hlf2, hlf2);
            __half2 narg = __hfma2(r2, hn2, __hfma2(xt2, win2, cnx2));
            __half2 n2 = htanh2(narg);

            // ---- fp32 state update per batch ----
            float2 zf = __half22float2(z2);
            float2 nf = __half22float2(n2);
            ha = fmaf(zf.x, ha - nf.x, nf.x);
            hb = fmaf(zf.y, hb - nf.y, nf.y);
        }
    }

    // Head: out[b][o] = sum_i h_i * head_w[o][i] + head_b[o]  (fp32)
    float p0a = ha * head_w[i], p1a = ha * head_w[32 + i];
    float p0b = hb * head_w[i], p1b = hb * head_w[32 + i];
    #pragma unroll
    for (int m = 16; m > 0; m >>= 1) {
        p0a += __shfl_xor_sync(FULL_MASK, p0a, m);
        p1a += __shfl_xor_sync(FULL_MASK, p1a, m);
        p0b += __shfl_xor_sync(FULL_MASK, p0b, m);
        p1b += __shfl_xor_sync(FULL_MASK, p1b, m);
    }
    if (i == 0) {
        out[2 * b0]     = p0a + head_b[0];
        out[2 * b0 + 1] = p1a + head_b[1];
        out[2 * b0 + 2] = p0b + head_b[0];
        out[2 * b0 + 3] = p1b + head_b[1];
    }
}

extern "C" void kernel_launch(void* const* d_in, const int* in_sizes, int n_in,
                              void* d_out, int out_size) {
    const float* x      = (const float*)d_in[0];
    const float* w_ih   = (const float*)d_in[1];
    const float* w_hh   = (const float*)d_in[2];
    const float* b_ih   = (const float*)d_in[3];
    const float* b_hh   = (const float*)d_in[4];
    const float* head_w = (const float*)d_in[5];
    const float* head_b = (const float*)d_in[6];
    float* out = (float*)d_out;

    const int B = out_size / 2;           // 2048
    const int T = in_sizes[0] / B;        // 2048

    gru_kernel<<<B / 2, 32>>>(x, w_ih, w_hh, b_ih, b_hh, head_w, head_b, out, B, T);
}

// round 7
// speedup vs baseline: 1.5596x; 1.0140x over previous
#include <cuda_runtime.h>
#include <cuda_fp16.h>

// SimpleGRU: B=2048, T=2048, H=32, scalar input.
// One warp = two batch elements; lane i = hidden unit i of both.
// INTERLEAVED-BATCH PACKING: state h2 = {hA_i, hB_i} as half2; weights
// duplicated {w,w}; matvec accumulators come out packed per gate, so the
// whole cross-batch shuffle tree disappears. Everything in the loop is fp16.
//   r,z rows prescaled by 0.5 (sigmoid via tanh.approx.f16x2).
// h broadcast via double-buffered smem (1 STS.32 + 1 syncwarp + 8 LDS.128).

#define FULL_MASK 0xffffffffu

__device__ __forceinline__ __half2 htanh2(__half2 a) {
    unsigned int d, s = *reinterpret_cast<unsigned int*>(&a);
    asm("tanh.approx.f16x2 %0, %1;" : "=r"(d) : "r"(s));
    return *reinterpret_cast<__half2*>(&d);
}
__device__ __forceinline__ __half2 u2h(unsigned int u) {
    return *reinterpret_cast<const __half2*>(&u);
}
__device__ __forceinline__ unsigned int h2u(__half2 h) {
    return *reinterpret_cast<unsigned int*>(&h);
}

__global__ void __launch_bounds__(32)
gru_kernel(const float* __restrict__ x,
           const float* __restrict__ w_ih,
           const float* __restrict__ w_hh,
           const float* __restrict__ b_ih,
           const float* __restrict__ b_hh,
           const float* __restrict__ head_w,
           const float* __restrict__ head_b,
           float* __restrict__ out,
           int B, int T)
{
    const int b0 = blockIdx.x * 2;          // two batch elements per warp
    const int i  = threadIdx.x;             // lane == hidden unit, H == 32

    // [parity][unit j] -> packed {hA_j, hB_j}
    __shared__ __align__(16) unsigned int hsh[2][32];

    // Duplicated {w,w} W_hh rows for unit i; r,z prescaled by 0.5.
    __half2 wr[32], wz[32], wn[32];
    {
        const float* Wr = w_hh + (0  + i) * 32;
        const float* Wz = w_hh + (32 + i) * 32;
        const float* Wn = w_hh + (64 + i) * 32;
        #pragma unroll
        for (int j = 0; j < 32; j++) {
            wr[j] = __float2half2_rn(Wr[j] * 0.5f);
            wz[j] = __float2half2_rn(Wz[j] * 0.5f);
            wn[j] = __float2half2_rn(Wn[j]);
        }
    }

    // x-side constants, duplicated into both lanes.
    const __half2 wir2 = __float2half2_rn(w_ih[i]      * 0.5f);
    const __half2 cr2  = __float2half2_rn((b_ih[i]      + b_hh[i])      * 0.5f);
    const __half2 wiz2 = __float2half2_rn(w_ih[32 + i] * 0.5f);
    const __half2 cz2  = __float2half2_rn((b_ih[32 + i] + b_hh[32 + i]) * 0.5f);
    const __half2 win2 = __float2half2_rn(w_ih[64 + i]);
    const __half2 cnx2 = __float2half2_rn(b_ih[64 + i]);
    const __half2 cnh2 = __float2half2_rn(b_hh[64 + i]);   // n-gate h-side bias
    const __half2 hlf2 = __float2half2_rn(0.5f);

    __half2 h2 = __float2half2_rn(0.0f);    // packed state {hA_i, hB_i}
    const float* xA = x + (long long)b0 * T;
    const float* xB = xA + T;

    for (int t0 = 0; t0 < T; t0 += 32) {
        // Pre-pack this lane's timestep inputs for both batches once per 32 steps.
        unsigned int xp = h2u(__floats2half2_rn(xA[t0 + i], xB[t0 + i]));
        #pragma unroll 4
        for (int k = 0; k < 32; k++) {
            __half2 xt2 = u2h(__shfl_sync(FULL_MASK, xp, k));
            const int p = k & 1;            // buffer parity

            hsh[p][i] = h2u(h2);            // one raw STS.32
            __syncwarp();                   // visible; WAR safe via parity

            // 8x LDS.128 broadcast: all 32 packed h pairs.
            const uint4* hp = (const uint4*)&hsh[p][0];
            uint4 q0 = hp[0], q1 = hp[1], q2 = hp[2], q3 = hp[3];
            uint4 q4 = hp[4], q5 = hp[5], q6 = hp[6], q7 = hp[7];
            unsigned int H[32] = {q0.x,q0.y,q0.z,q0.w, q1.x,q1.y,q1.z,q1.w,
                                  q2.x,q2.y,q2.z,q2.w, q3.x,q3.y,q3.z,q3.w,
                                  q4.x,q4.y,q4.z,q4.w, q5.x,q5.y,q5.z,q5.w,
                                  q6.x,q6.y,q6.z,q6.w, q7.x,q7.y,q7.z,q7.w};

            // Matvec: 4 chains per gate (depth 8), accumulators packed {A,B}.
            __half2 r0 = __hmul2(wr[0], u2h(H[0]));
            __half2 r1 = __hmul2(wr[1], u2h(H[1]));
            __half2 r2_ = __hmul2(wr[2], u2h(H[2]));
            __half2 r3 = __hmul2(wr[3], u2h(H[3]));
            __half2 z0 = __hmul2(wz[0], u2h(H[0]));
            __half2 z1 = __hmul2(wz[1], u2h(H[1]));
            __half2 z2_ = __hmul2(wz[2], u2h(H[2]));
            __half2 z3 = __hmul2(wz[3], u2h(H[3]));
            __half2 n0 = __hfma2(wn[0], u2h(H[0]), cnh2);
            __half2 n1 = __hmul2(wn[1], u2h(H[1]));
            __half2 n2_ = __hmul2(wn[2], u2h(H[2]));
            __half2 n3 = __hmul2(wn[3], u2h(H[3]));
            #pragma unroll
            for (int j = 4; j < 32; j += 4) {
                __half2 g0 = u2h(H[j]),   g1 = u2h(H[j+1]);
                __half2 g2 = u2h(H[j+2]), g3 = u2h(H[j+3]);
                r0  = __hfma2(wr[j],   g0, r0);
                r1  = __hfma2(wr[j+1], g1, r1);
                r2_ = __hfma2(wr[j+2], g2, r2_);
                r3  = __hfma2(wr[j+3], g3, r3);
                z0  = __hfma2(wz[j],   g0, z0);
                z1  = __hfma2(wz[j+1], g1, z1);
                z2_ = __hfma2(wz[j+2], g2, z2_);
                z3  = __hfma2(wz[j+3], g3, z3);
                n0  = __hfma2(wn[j],   g0, n0);
                n1  = __hfma2(wn[j+1], g1, n1);
                n2_ = __hfma2(wn[j+2], g2, n2_);
                n3  = __hfma2(wn[j+3], g3, n3);
            }
            __half2 hr2 = __hadd2(__hadd2(r0, r1), __hadd2(r2_, r3));
            __half2 hz2 = __hadd2(__hadd2(z0, z1), __hadd2(z2_, z3));
            __half2 hn2 = __hadd2(__hadd2(n0, n1), __hadd2(n2_, n3));

            // Packed gate math over {A, B}.
            __half2 pre_r = __hadd2(hr2, __hfma2(xt2, wir2, cr2));   // 0.5*preact
            __half2 pre_z = __hadd2(hz2, __hfma2(xt2, wiz2, cz2));
            __half2 rg = __hfma2(htanh2(pre_r), hlf2, hlf2);         // sigmoid
            __half2 zg = __hfma2(htanh2(pre_z), hlf2, hlf2);
            __half2 narg = __hfma2(rg, hn2, __hfma2(xt2, win2, cnx2));
            __half2 ng = htanh2(narg);

            h2 = __hfma2(zg, __hsub2(h2, ng), ng);   // (1-z)*n + z*h, packed
        }
    }

    // Head: out[b][o] = sum_i h_i * head_w[o][i] + head_b[o]  (fp32)
    float2 hf = __half22float2(h2);
    float ha = hf.x, hb = hf.y;
    float p0a = ha * head_w[i], p1a = ha * head_w[32 + i];
    float p0b = hb * head_w[i], p1b = hb * head_w[32 + i];
    #pragma unroll
    for (int m = 16; m > 0; m >>= 1) {
        p0a += __shfl_xor_sync(FULL_MASK, p0a, m);
        p1a += __shfl_xor_sync(FULL_MASK, p1a, m);
        p0b += __shfl_xor_sync(FULL_MASK, p0b, m);
        p1b += __shfl_xor_sync(FULL_MASK, p1b, m);
    }
    if (i == 0) {
        out[2 * b0]     = p0a + head_b[0];
        out[2 * b0 + 1] = p1a + head_b[1];
        out[2 * b0 + 2] = p0b + head_b[0];
        out[2 * b0 + 3] = p1b + head_b[1];
    }
}

extern "C" void kernel_launch(void* const* d_in, const int* in_sizes, int n_in,
                              void* d_out, int out_size) {
    const float* x      = (const float*)d_in[0];
    const float* w_ih   = (const float*)d_in[1];
    const float* w_hh   = (const float*)d_in[2];
    const float* b_ih   = (const float*)d_in[3];
    const float* b_hh   = (const float*)d_in[4];
    const float* head_w = (const float*)d_in[5];
    const float* head_b = (const float*)d_in[6];
    float* out = (float*)d_out;

    const int B = out_size / 2;           // 2048
    const int T = in_sizes[0] / B;        // 2048

    gru_kernel<<<B / 2, 32>>>(x, w_ih, w_hh, b_ih, b_hh, head_w, head_b, out, B, T);
}